// round 13
// baseline (speedup 1.0000x reference)
#include <cuda_runtime.h>
#include <cuda_fp16.h>
#include <cstdint>

// ColBERT MaxSim on GB300 (sm_103): persistent balanced main (one wave, chunk-
// granular split, atomicMax staging) with finalization folded into the tail of
// the main kernel (last-32-arrivers scheme). Two launches total.
// qs: (64, 32, 128) fp32 ; ps: (64, 1024, 128) fp32 ; out: (64, 64) fp32

#define NQ       64
#define TQ       32
#define ND       64
#define TS       1024
#define DIM      128
#define G_Q      4
#define THREADS  128
#define SN       64                    // doc tokens per chunk
#define CPS      16                    // chunks per segment
#define NSEG     (ND * (NQ / G_Q))     // 1024 segments (qg x doc)
#define NCTA     592                   // 148 SMs x 4 CTAs (one wave)
#define BIGCTAS  400                   // 400*28 + 192*27 = 16384 units
#define NFIN     32                    // finisher CTAs (last arrivers)
#define ROWB     256
#define BUFB     (SN * ROWB)           // 16 KB
#define U_TOK    (DIM / 8)

__device__ uint4    scratch_ps_v[(size_t)ND * TS * DIM / 8];   // 16 MB
__device__ unsigned g_stage[NSEG * 128];                       // 512 KB
__device__ unsigned g_done;

#define ENC_NEGINF 0x007FFFFFu

__device__ __forceinline__ unsigned enc_f(float f) {
    unsigned u = __float_as_uint(f);
    return (u & 0x80000000u) ? ~u : (u | 0x80000000u);
}
__device__ __forceinline__ float dec_f(unsigned k) {
    unsigned u = (k & 0x80000000u) ? (k & 0x7FFFFFFFu) : ~k;
    return __uint_as_float(u);
}
__device__ __forceinline__ unsigned ld_acq(const unsigned* p) {
    unsigned v;
    asm volatile("ld.acquire.gpu.global.u32 %0, [%1];" : "=r"(v) : "l"(p));
    return v;
}

// fp32->f16 convert + staging/counter init (runs before main every launch)
__global__ void cvt_ps_kernel(const float4* __restrict__ src) {
    int i = blockIdx.x * blockDim.x + threadIdx.x;    // 524288 threads
    float4 a0 = src[4 * i],     a1 = src[4 * i + 1];
    float4 b0 = src[4 * i + 2], b1 = src[4 * i + 3];
    uint4 o0, o1; __half2 h;
    h = __floats2half2_rn(a0.x, a0.y); o0.x = *reinterpret_cast<uint32_t*>(&h);
    h = __floats2half2_rn(a0.z, a0.w); o0.y = *reinterpret_cast<uint32_t*>(&h);
    h = __floats2half2_rn(a1.x, a1.y); o0.z = *reinterpret_cast<uint32_t*>(&h);
    h = __floats2half2_rn(a1.z, a1.w); o0.w = *reinterpret_cast<uint32_t*>(&h);
    h = __floats2half2_rn(b0.x, b0.y); o1.x = *reinterpret_cast<uint32_t*>(&h);
    h = __floats2half2_rn(b0.z, b0.w); o1.y = *reinterpret_cast<uint32_t*>(&h);
    h = __floats2half2_rn(b1.x, b1.y); o1.z = *reinterpret_cast<uint32_t*>(&h);
    h = __floats2half2_rn(b1.z, b1.w); o1.w = *reinterpret_cast<uint32_t*>(&h);
    scratch_ps_v[2 * i]     = o0;
    scratch_ps_v[2 * i + 1] = o1;
    if (i < NSEG * 128) g_stage[i] = ENC_NEGINF;
    if (i == 0) g_done = 0u;
}

__device__ __forceinline__ uint32_t smem_u32(const void* p) {
    uint32_t a;
    asm("{ .reg .u64 t; cvta.to.shared.u64 t, %1; cvt.u32.u64 %0, t; }" : "=r"(a) : "l"(p));
    return a;
}
__device__ __forceinline__ unsigned pack_h2(float lo, float hi) {
    __half2 h = __floats2half2_rn(lo, hi);
    return *reinterpret_cast<unsigned*>(&h);
}
__device__ __forceinline__ void mma_f16(float c[4],
                                        unsigned a0, unsigned a1, unsigned a2, unsigned a3,
                                        unsigned b0, unsigned b1) {
    asm volatile(
        "mma.sync.aligned.m16n8k16.row.col.f32.f16.f16.f32 "
        "{%0,%1,%2,%3}, {%4,%5,%6,%7}, {%8,%9}, {%0,%1,%2,%3};\n"
        : "+f"(c[0]), "+f"(c[1]), "+f"(c[2]), "+f"(c[3])
        : "r"(a0), "r"(a1), "r"(a2), "r"(a3), "r"(b0), "r"(b1));
}

__global__ __launch_bounds__(THREADS, 4)
void colbert_kernel(const float* __restrict__ qs, float* __restrict__ out) {
    __shared__ __align__(1024) char Bs[2 * BUFB];
    __shared__ unsigned s_rank;

    const int tid   = threadIdx.x;
    const int w     = tid >> 5;
    const int lane  = tid & 31;
    const int g     = lane >> 2;
    const int t     = lane & 3;
    const uint32_t sb = smem_u32(Bs);
    const int rl = lane & 7;
    const int mc = lane >> 3;

    const int bid = blockIdx.x;
    int u  = (bid < BIGCTAS) ? bid * 28 : BIGCTAS * 28 + (bid - BIGCTAS) * 27;
    const int u1 = u + ((bid < BIGCTAS) ? 28 : 27);

    unsigned Af[2][8][4];
    int prev_qg = -1;

    #pragma unroll 1
    while (u < u1) {
        const int seg  = u >> 4;          // seg = qg*64 + doc
        const int qg   = seg >> 6;
        const int doc  = seg & 63;
        const int c0   = u & 15;
        const int cend = min(u1 - (seg << 4), CPS);

        const uint4* gsrc = scratch_ps_v + (size_t)doc * TS * U_TOK;

        __syncthreads();   // prior segment's readers done before buf0 overwrite

        {
            const uint4* bq = gsrc + (size_t)c0 * SN * U_TOK;
            #pragma unroll
            for (int j = 0; j < 8; j++) {
                int f = j * THREADS + tid;
                int r = f >> 4, cc = f & 15;
                uint32_t dst = sb + r * ROWB + ((cc ^ (r & 7)) << 4);
                asm volatile("cp.async.cg.shared.global [%0], [%1], 16;\n" :: "r"(dst), "l"(bq + f));
            }
            asm volatile("cp.async.commit_group;\n");
        }

        if (qg != prev_qg) {
            prev_qg = qg;
            const int rbase = (qg * G_Q + w) * TQ;
            #pragma unroll
            for (int mt = 0; mt < 2; mt++) {
                #pragma unroll
                for (int ks = 0; ks < 8; ks++) {
                    const int r0 = rbase + mt * 16 + g;
                    const int cc = ks * 16 + t * 2;
                    const float2* p0 = reinterpret_cast<const float2*>(qs + (size_t)r0 * DIM + cc);
                    const float2* p1 = reinterpret_cast<const float2*>(qs + (size_t)(r0 + 8) * DIM + cc);
                    float2 v00 = p0[0];
                    float2 v02 = p0[4];
                    float2 v10 = p1[0];
                    float2 v12 = p1[4];
                    Af[mt][ks][0] = pack_h2(v00.x, v00.y);
                    Af[mt][ks][1] = pack_h2(v10.x, v10.y);
                    Af[mt][ks][2] = pack_h2(v02.x, v02.y);
                    Af[mt][ks][3] = pack_h2(v12.x, v12.y);
                }
            }
        }

        float rmax0 = -1e30f, rmax1 = -1e30f, rmax2 = -1e30f, rmax3 = -1e30f;

        #pragma unroll 1
        for (int c = c0; c < cend; c++) {
            const int lc = c - c0;
            asm volatile("cp.async.wait_group 0;\n");
            __syncthreads();

            if (c + 1 < cend) {
                const uint4* gs2  = gsrc + (size_t)(c + 1) * SN * U_TOK;
                uint32_t     dbuf = sb + ((lc + 1) & 1) * BUFB;
                #pragma unroll
                for (int j = 0; j < 8; j++) {
                    int f = j * THREADS + tid;
                    int r = f >> 4, cc = f & 15;
                    uint32_t dst = dbuf + r * ROWB + ((cc ^ (r & 7)) << 4);
                    asm volatile("cp.async.cg.shared.global [%0], [%1], 16;\n" :: "r"(dst), "l"(gs2 + f));
                }
                asm volatile("cp.async.commit_group;\n");
            }

            const uint32_t cbase = sb + (lc & 1) * BUFB + rl * ROWB;
            #pragma unroll
            for (int nf = 0; nf < 8; nf++) {
                float cA[4] = {0.f, 0.f, 0.f, 0.f};
                float cB[4] = {0.f, 0.f, 0.f, 0.f};
                #pragma unroll
                for (int kp = 0; kp < 4; kp++) {
                    uint32_t addr = cbase + nf * 8 * ROWB + ((((kp << 2) | mc) ^ rl) << 4);
                    uint32_t b0, b1, b2, b3;
                    asm volatile("ldmatrix.sync.aligned.m8n8.x4.shared.b16 {%0,%1,%2,%3}, [%4];\n"
                                 : "=r"(b0), "=r"(b1), "=r"(b2), "=r"(b3) : "r"(addr));
                    mma_f16(cA, Af[0][2*kp][0],   Af[0][2*kp][1],   Af[0][2*kp][2],   Af[0][2*kp][3],   b0, b1);
                    mma_f16(cB, Af[1][2*kp][0],   Af[1][2*kp][1],   Af[1][2*kp][2],   Af[1][2*kp][3],   b0, b1);
                    mma_f16(cA, Af[0][2*kp+1][0], Af[0][2*kp+1][1], Af[0][2*kp+1][2], Af[0][2*kp+1][3], b2, b3);
                    mma_f16(cB, Af[1][2*kp+1][0], Af[1][2*kp+1][1], Af[1][2*kp+1][2], Af[1][2*kp+1][3], b2, b3);
                }
                rmax0 = fmaxf(rmax0, fmaxf(cA[0], cA[1]));
                rmax1 = fmaxf(rmax1, fmaxf(cA[2], cA[3]));
                rmax2 = fmaxf(rmax2, fmaxf(cB[0], cB[1]));
                rmax3 = fmaxf(rmax3, fmaxf(cB[2], cB[3]));
            }
        }

        #pragma unroll
        for (int off = 1; off <= 2; off <<= 1) {
            rmax0 = fmaxf(rmax0, __shfl_xor_sync(0xffffffffu, rmax0, off));
            rmax1 = fmaxf(rmax1, __shfl_xor_sync(0xffffffffu, rmax1, off));
            rmax2 = fmaxf(rmax2, __shfl_xor_sync(0xffffffffu, rmax2, off));
            rmax3 = fmaxf(rmax3, __shfl_xor_sync(0xffffffffu, rmax3, off));
        }
        if (t == 0) {
            unsigned* s = g_stage + (size_t)seg * 128 + w * 32;
            atomicMax(&s[g],      enc_f(rmax0));
            atomicMax(&s[g + 8],  enc_f(rmax1));
            atomicMax(&s[g + 16], enc_f(rmax2));
            atomicMax(&s[g + 24], enc_f(rmax3));
        }

        u = (seg << 4) + cend;
    }

    // ---- tail: arrival counter; last NFIN arrivers finalize outputs ----
    if (tid == 0) {
        __threadfence();
        s_rank = atomicAdd(&g_done, 1u);   // old value = arrival rank
    }
    __syncthreads();
    const unsigned rank = s_rank;
    if (rank >= NCTA - NFIN) {
        if (tid == 0) {
            while (ld_acq(&g_done) < NCTA) { }
        }
        __syncthreads();
        // slice of 4096/NFIN = 128 outputs; 1 output per thread
        const int o  = (int)(rank - (NCTA - NFIN)) * 128 + tid;
        const int b  = o >> 6, c = o & 63;
        const int qg = b >> 2, wq = b & 3;
        const unsigned* s = g_stage + ((size_t)(qg * ND + c)) * 128 + wq * 32;
        float v = 0.f;
        #pragma unroll
        for (int j = 0; j < 8; j++) {
            uint4 k;
            asm volatile("ld.global.cg.v4.u32 {%0,%1,%2,%3}, [%4];"
                         : "=r"(k.x), "=r"(k.y), "=r"(k.z), "=r"(k.w)
                         : "l"(reinterpret_cast<const uint4*>(s) + j));
            v += dec_f(k.x) + dec_f(k.y) + dec_f(k.z) + dec_f(k.w);
        }
        out[b * ND + c] = v;
    }
}

extern "C" void kernel_launch(void* const* d_in, const int* in_sizes, int n_in,
                              void* d_out, int out_size) {
    const float* qs = (const float*)d_in[0];   // 64*32*128
    const float* ps = (const float*)d_in[1];   // 64*1024*128
    float* out = (float*)d_out;                // 64*64

    cvt_ps_kernel<<<(ND * TS * DIM / 16) / 256, 256>>>((const float4*)ps);
    colbert_kernel<<<NCTA, THREADS>>>(qs, out);
}

// round 14
// speedup vs baseline: 1.0731x; 1.0731x over previous
#include <cuda_runtime.h>
#include <cuda_fp16.h>
#include <cstdint>

// ColBERT MaxSim on GB300 (sm_103): R4 core + software-pipelined ldmatrix.
// Two launches: cvt (fp32->f16 ps) + main (mma.sync f16, cp.async double buffer).
// qs: (64, 32, 128) fp32 ; ps: (64, 1024, 128) fp32 ; out: (64, 64) fp32

#define NQ       64
#define TQ       32
#define ND       64
#define TS       1024
#define DIM      128
#define G_Q      4                    // queries per CTA (1 per warp)
#define THREADS  128
#define SN       64                   // doc tokens per chunk
#define NCHUNK   (TS / SN)            // 16
#define ROWB     256                  // bytes per token row in smem (128 f16)
#define BUFB     (SN * ROWB)          // 16 KB per buffer

// fp16 ps scratch (device-global; allocation-free per harness rules)
__device__ uint4 scratch_ps_v[(size_t)ND * TS * DIM / 8];   // 16 MB

__global__ void cvt_ps_kernel(const float4* __restrict__ src) {
    int i = blockIdx.x * blockDim.x + threadIdx.x;    // 524288 threads
    float4 a0 = src[4 * i],     a1 = src[4 * i + 1];
    float4 b0 = src[4 * i + 2], b1 = src[4 * i + 3];
    uint4 o0, o1; __half2 h;
    h = __floats2half2_rn(a0.x, a0.y); o0.x = *reinterpret_cast<uint32_t*>(&h);
    h = __floats2half2_rn(a0.z, a0.w); o0.y = *reinterpret_cast<uint32_t*>(&h);
    h = __floats2half2_rn(a1.x, a1.y); o0.z = *reinterpret_cast<uint32_t*>(&h);
    h = __floats2half2_rn(a1.z, a1.w); o0.w = *reinterpret_cast<uint32_t*>(&h);
    h = __floats2half2_rn(b0.x, b0.y); o1.x = *reinterpret_cast<uint32_t*>(&h);
    h = __floats2half2_rn(b0.z, b0.w); o1.y = *reinterpret_cast<uint32_t*>(&h);
    h = __floats2half2_rn(b1.x, b1.y); o1.z = *reinterpret_cast<uint32_t*>(&h);
    h = __floats2half2_rn(b1.z, b1.w); o1.w = *reinterpret_cast<uint32_t*>(&h);
    scratch_ps_v[2 * i]     = o0;
    scratch_ps_v[2 * i + 1] = o1;
}

__device__ __forceinline__ uint32_t smem_u32(const void* p) {
    uint32_t a;
    asm("{ .reg .u64 t; cvta.to.shared.u64 t, %1; cvt.u32.u64 %0, t; }" : "=r"(a) : "l"(p));
    return a;
}
__device__ __forceinline__ unsigned pack_h2(float lo, float hi) {
    __half2 h = __floats2half2_rn(lo, hi);
    return *reinterpret_cast<unsigned*>(&h);
}
__device__ __forceinline__ void mma_f16(float c[4],
                                        unsigned a0, unsigned a1, unsigned a2, unsigned a3,
                                        unsigned b0, unsigned b1) {
    asm volatile(
        "mma.sync.aligned.m16n8k16.row.col.f32.f16.f16.f32 "
        "{%0,%1,%2,%3}, {%4,%5,%6,%7}, {%8,%9}, {%0,%1,%2,%3};\n"
        : "+f"(c[0]), "+f"(c[1]), "+f"(c[2]), "+f"(c[3])
        : "r"(a0), "r"(a1), "r"(a2), "r"(a3), "r"(b0), "r"(b1));
}
#define LDM_X4(reg, addr)                                                          \
    asm volatile("ldmatrix.sync.aligned.m8n8.x4.shared.b16 {%0,%1,%2,%3}, [%4];\n" \
                 : "=r"((reg)[0]), "=r"((reg)[1]), "=r"((reg)[2]), "=r"((reg)[3])  \
                 : "r"(addr))

__global__ __launch_bounds__(THREADS, 4)
void colbert_kernel(const float* __restrict__ qs, float* __restrict__ out) {
    __shared__ __align__(1024) char Bs[2 * BUFB];

    const int tid   = threadIdx.x;
    const int w     = tid >> 5;          // warp = query within group
    const int lane  = tid & 31;
    const int g     = lane >> 2;
    const int t     = lane & 3;
    const int c_doc = blockIdx.x;
    const int qg    = blockIdx.y;
    const uint32_t sb = smem_u32(Bs);

    const uint4* gsrc = scratch_ps_v + (size_t)c_doc * TS * (DIM / 8);

    // ---- prologue: async-copy chunk 0 into buffer 0 (XOR-swizzled rows) ----
    #pragma unroll
    for (int j = 0; j < 8; j++) {
        int f = j * THREADS + tid;       // 16B unit index, 1024 per chunk
        int r = f >> 4;                  // token row (16 units per 256B row)
        int c = f & 15;
        uint32_t dst = sb + r * ROWB + ((c ^ (r & 7)) << 4);
        asm volatile("cp.async.cg.shared.global [%0], [%1], 16;\n" :: "r"(dst), "l"(gsrc + f));
    }
    asm volatile("cp.async.commit_group;\n");

    // ---- A fragments: this warp's query (32 rows x 128 dims), fp32 -> f16 ----
    unsigned Af[2][8][4];
    {
        const int rbase = (qg * G_Q + w) * TQ;
        #pragma unroll
        for (int mt = 0; mt < 2; mt++) {
            #pragma unroll
            for (int ks = 0; ks < 8; ks++) {
                const int r0 = rbase + mt * 16 + g;
                const int cc = ks * 16 + t * 2;
                const float2* p0 = reinterpret_cast<const float2*>(qs + (size_t)r0 * DIM + cc);
                const float2* p1 = reinterpret_cast<const float2*>(qs + (size_t)(r0 + 8) * DIM + cc);
                float2 v00 = p0[0];
                float2 v02 = p0[4];
                float2 v10 = p1[0];
                float2 v12 = p1[4];
                Af[mt][ks][0] = pack_h2(v00.x, v00.y);
                Af[mt][ks][1] = pack_h2(v10.x, v10.y);
                Af[mt][ks][2] = pack_h2(v02.x, v02.y);
                Af[mt][ks][3] = pack_h2(v12.x, v12.y);
            }
        }
    }

    float rmax0 = -1e30f, rmax1 = -1e30f, rmax2 = -1e30f, rmax3 = -1e30f;

    const int rl = lane & 7;             // B: row provider within 8x8 matrix
    const int mc = lane >> 3;            // B: matrix select

    #pragma unroll 1
    for (int ch = 0; ch < NCHUNK; ch++) {
        asm volatile("cp.async.wait_group 0;\n");
        __syncthreads();

        if (ch + 1 < NCHUNK) {
            const uint4* gs2  = gsrc + (size_t)(ch + 1) * SN * (DIM / 8);
            uint32_t     dbuf = sb + ((ch + 1) & 1) * BUFB;
            #pragma unroll
            for (int j = 0; j < 8; j++) {
                int f = j * THREADS + tid;
                int r = f >> 4;
                int c = f & 15;
                uint32_t dst = dbuf + r * ROWB + ((c ^ (r & 7)) << 4);
                asm volatile("cp.async.cg.shared.global [%0], [%1], 16;\n" :: "r"(dst), "l"(gs2 + f));
            }
            asm volatile("cp.async.commit_group;\n");
        }

        // ---- compute on buffer ch&1, software-pipelined ldmatrix (1 ahead) ----
        const uint32_t cbase = sb + (ch & 1) * BUFB + rl * ROWB;
        uint32_t B[2][4];
        float cA[4], cB[4];
        LDM_X4(B[0], cbase + ((mc ^ rl) << 4));         // step 0: nf=0, kp=0
        #pragma unroll
        for (int p = 0; p < 32; p++) {                  // p = nf*4 + kp
            const int kp = p & 3;
            if (p + 1 < 32) {
                const int nf2 = (p + 1) >> 2;
                const int kp2 = (p + 1) & 3;
                LDM_X4(B[(p + 1) & 1],
                       cbase + nf2 * 8 * ROWB + ((((kp2 << 2) | mc) ^ rl) << 4));
            }
            const uint32_t* b = B[p & 1];
            if (kp == 0) {
                cA[0] = cA[1] = cA[2] = cA[3] = 0.f;
                cB[0] = cB[1] = cB[2] = cB[3] = 0.f;
            }
            mma_f16(cA, Af[0][2*kp][0],   Af[0][2*kp][1],   Af[0][2*kp][2],   Af[0][2*kp][3],   b[0], b[1]);
            mma_f16(cB, Af[1][2*kp][0],   Af[1][2*kp][1],   Af[1][2*kp][2],   Af[1][2*kp][3],   b[0], b[1]);
            mma_f16(cA, Af[0][2*kp+1][0], Af[0][2*kp+1][1], Af[0][2*kp+1][2], Af[0][2*kp+1][3], b[2], b[3]);
            mma_f16(cB, Af[1][2*kp+1][0], Af[1][2*kp+1][1], Af[1][2*kp+1][2], Af[1][2*kp+1][3], b[2], b[3]);
            if (kp == 3) {
                rmax0 = fmaxf(rmax0, fmaxf(cA[0], cA[1]));
                rmax1 = fmaxf(rmax1, fmaxf(cA[2], cA[3]));
                rmax2 = fmaxf(rmax2, fmaxf(cB[0], cB[1]));
                rmax3 = fmaxf(rmax3, fmaxf(cB[2], cB[3]));
            }
        }
    }

    // ---- reduce: complete row maxes across the 4 lanes sharing g ----
    #pragma unroll
    for (int off = 1; off <= 2; off <<= 1) {
        rmax0 = fmaxf(rmax0, __shfl_xor_sync(0xffffffffu, rmax0, off));
        rmax1 = fmaxf(rmax1, __shfl_xor_sync(0xffffffffu, rmax1, off));
        rmax2 = fmaxf(rmax2, __shfl_xor_sync(0xffffffffu, rmax2, off));
        rmax3 = fmaxf(rmax3, __shfl_xor_sync(0xffffffffu, rmax3, off));
    }
    float v = rmax0 + rmax1 + rmax2 + rmax3;   // rows {g, g+8, g+16, g+24}
    v += __shfl_xor_sync(0xffffffffu, v, 4);
    v += __shfl_xor_sync(0xffffffffu, v, 8);
    v += __shfl_xor_sync(0xffffffffu, v, 16);

    if (lane == 0) {
        out[(qg * G_Q + w) * ND + c_doc] = v;
    }
}

extern "C" void kernel_launch(void* const* d_in, const int* in_sizes, int n_in,
                              void* d_out, int out_size) {
    const float* qs = (const float*)d_in[0];   // 64*32*128
    const float* ps = (const float*)d_in[1];   // 64*1024*128
    float* out = (float*)d_out;                // 64*64

    cvt_ps_kernel<<<(ND * TS * DIM / 16) / 256, 256>>>((const float4*)ps);

    dim3 grid(ND, NQ / G_Q);                   // (64 docs, 16 query groups)
    colbert_kernel<<<grid, THREADS>>>(qs, out);
}